// round 12
// baseline (speedup 1.0000x reference)
#include <cuda_runtime.h>
#include <cstdint>

// AUGRU: B=65536, T=50, E=10.
// Fold: (x@Wi + bi + h@Wh)@Ws + bs == x@(Wi@Ws) + h@(Wh@Ws) + (bi@Ws + bs)
// R11 = R9 (feature-packed f32x2, 2 elems/thread, const/smem weight split,
// tanh.approx, 1024 warps) + cross-timestep software pipelining: the r/z
// x-side dot partials for step t+1 (h-independent, ~200 fma2 + 60 LDC) are
// computed during iteration t, overlapping the serial h-chain. 4-buffer
// cp.async ring staged 2 steps ahead. No syncwarp (threads read only rows
// they staged themselves).

#define E_  10
#define T_  50
#define B_  65536
#define NB  32           // threads per block
#define EB  64           // batch elems per block (2 per thread)
#define RS  10           // floats per row per timestep
#define ROWB (T_*E_)     // 500 floats per batch row
#define NBUF 4

// g_w2 layout (transposed A^T[j][k], row stride 12, 16B-aligned rows):
//   const part: Axr@0, Axz@120, Axh@240, biases br@360 bz@370 bh@380
//   smem part:  Ahr@400, Ahz@520, Ahh@640   (also stride 12)
__device__ float g_w2[880];

// constant mirror of g_w2[0..389]
__constant__ float c_w[390];

__global__ void augru_precompute(
    const float* __restrict__ Wi_r, const float* __restrict__ bi_r,
    const float* __restrict__ Wh_r, const float* __restrict__ Ws_r, const float* __restrict__ bs_r,
    const float* __restrict__ Wi_z, const float* __restrict__ bi_z,
    const float* __restrict__ Wh_z, const float* __restrict__ Ws_z, const float* __restrict__ bs_z,
    const float* __restrict__ Wi_h, const float* __restrict__ bi_h,
    const float* __restrict__ Wh_h, const float* __restrict__ Wt_h, const float* __restrict__ bt_h)
{
    int tid = threadIdx.x;
    if (tid < 600) {
        int m = tid / 100, rem = tid % 100, j = rem / 10, k = rem % 10;
        const float* W1; const float* W2; int dst;
        switch (m) {
            case 0: W1 = Wi_r; W2 = Ws_r; dst = 0;   break;  // Axr (const)
            case 1: W1 = Wh_r; W2 = Ws_r; dst = 400; break;  // Ahr (smem)
            case 2: W1 = Wi_z; W2 = Ws_z; dst = 120; break;  // Axz (const)
            case 3: W1 = Wh_z; W2 = Ws_z; dst = 520; break;  // Ahz (smem)
            case 4: W1 = Wi_h; W2 = Wt_h; dst = 240; break;  // Axh (const)
            default: W1 = Wh_h; W2 = Wt_h; dst = 640; break; // Ahh (smem)
        }
        float acc = 0.f;
        #pragma unroll
        for (int mm = 0; mm < E_; mm++)
            acc += W1[k * E_ + mm] * W2[mm * E_ + j];
        g_w2[dst + j * 12 + k] = acc;
    } else if (tid < 630) {
        int g = (tid - 600) / 10, j = (tid - 600) % 10;
        const float* bi; const float* Ws; const float* bs;
        if (g == 0)      { bi = bi_r; Ws = Ws_r; bs = bs_r; }
        else if (g == 1) { bi = bi_z; Ws = Ws_z; bs = bs_z; }
        else             { bi = bi_h; Ws = Wt_h; bs = bt_h; }
        float acc = bs[j];
        #pragma unroll
        for (int mm = 0; mm < E_; mm++)
            acc += bi[mm] * Ws[mm * E_ + j];
        g_w2[360 + g * 10 + j] = acc;
    }
}

__device__ __forceinline__ float2 fma2(float2 a, float2 b, float2 c) {
    unsigned long long ua = *reinterpret_cast<unsigned long long*>(&a);
    unsigned long long ub = *reinterpret_cast<unsigned long long*>(&b);
    unsigned long long uc = *reinterpret_cast<unsigned long long*>(&c);
    unsigned long long ud;
    asm("fma.rn.f32x2 %0, %1, %2, %3;" : "=l"(ud) : "l"(ua), "l"(ub), "l"(uc));
    return *reinterpret_cast<float2*>(&ud);
}

__device__ __forceinline__ float tanh_ap(float x) {
    float y;
    asm("tanh.approx.f32 %0, %1;" : "=f"(y) : "f"(x));
    return y;
}
__device__ __forceinline__ float sigf(float x) {
    return fmaf(0.5f, tanh_ap(0.5f * x), 0.5f);
}

// one 10-float weight row, loaded once (f4,f4,f2)
struct W10 { float4 a; float4 b; float2 c; };

__device__ __forceinline__ W10 ldrow(const float* __restrict__ w) {
    W10 r;
    r.a = *reinterpret_cast<const float4*>(w);
    r.b = *reinterpret_cast<const float4*>(w + 4);
    r.c = *reinterpret_cast<const float2*>(w + 8);
    return r;
}

// dot of loaded row with feature-packed vector v[5] into (even,odd) acc
__device__ __forceinline__ float2 dotw(const W10& w, const float2* __restrict__ v, float2 acc) {
    acc = fma2(make_float2(w.a.x, w.a.y), v[0], acc);
    acc = fma2(make_float2(w.a.z, w.a.w), v[1], acc);
    acc = fma2(make_float2(w.b.x, w.b.y), v[2], acc);
    acc = fma2(make_float2(w.b.z, w.b.w), v[3], acc);
    acc = fma2(w.c,                       v[4], acc);
    return acc;
}

// scalar access into feature-packed float2[5] with compile-time j
#define F2AT(arr, j) (((j) & 1) ? (arr)[(j) >> 1].y : (arr)[(j) >> 1].x)

__device__ __forceinline__ void cpa8(uint32_t smem_addr, const void* gptr) {
    asm volatile("cp.async.ca.shared.global [%0], [%1], 8;" :: "r"(smem_addr), "l"(gptr));
}

__global__ void __launch_bounds__(NB) augru_main(
    const float* __restrict__ gx,   // [B, T, E]
    const float* __restrict__ ga,   // [B, T, E]
    const float* __restrict__ h0,   // [1, E]
    float* __restrict__ out)        // [B, E]
{
    __shared__ __align__(16) float sw[360];            // h-side matrices, stride 12
    __shared__ __align__(16) float sx[NBUF][EB * RS];  // [buf][row][10]
    __shared__ __align__(16) float sa[NBUF][EB * RS];

    const int tid = threadIdx.x;
    const int b0  = blockIdx.x * EB;

    const uint32_t sxa = (uint32_t)__cvta_generic_to_shared(&sx[0][0]);
    const uint32_t saa = (uint32_t)__cvta_generic_to_shared(&sa[0][0]);
    const char* gxb = (const char*)gx + (size_t)b0 * (ROWB * 4);
    const char* gab = (const char*)ga + (size_t)b0 * (ROWB * 4);

    // stage timestep t into ring buffer d: thread copies its rows tid, tid+32
    auto stage = [&](int t, int d) {
        const int tb = t * (RS * 4);
        #pragma unroll
        for (int k = 0; k < 2; k++) {
            const int row = tid + k * NB;
            const uint32_t sbase = (uint32_t)((d * (EB * RS) + row * RS) * 4);
            const size_t gbase = (size_t)row * (ROWB * 4) + tb;
            #pragma unroll
            for (int c = 0; c < 5; c++) {
                cpa8(sxa + sbase + c * 8, gxb + gbase + c * 8);
                cpa8(saa + sbase + c * 8, gab + gbase + c * 8);
            }
        }
        asm volatile("cp.async.commit_group;");
    };

    stage(0, 0);
    stage(1, 1);

    for (int i = tid; i < 360; i += NB) sw[i] = g_w2[400 + i];

    const float* Ahr = sw + 0;
    const float* Ahz = sw + 120;
    const float* Ahh = sw + 240;

    // h feature-packed for 2 elements: unit u = batch row b0 + tid + 32u
    float2 h[2][5];
    #pragma unroll
    for (int i = 0; i < 5; i++) {
        float2 v = make_float2(h0[2 * i], h0[2 * i + 1]);
        h[0][i] = v; h[1][i] = v;
    }

    // wait for stage(0) (stage(1) may remain in flight)
    asm volatile("cp.async.wait_group 1;");

    // prologue: x(0) + its r/z x-side partials
    float2 xp_c[2][5];
    #pragma unroll
    for (int u = 0; u < 2; u++) {
        const float* xr = &sx[0][(tid + 32 * u) * RS];
        #pragma unroll
        for (int i = 0; i < 5; i++)
            xp_c[u][i] = *reinterpret_cast<const float2*>(xr + 2 * i);
    }

    float uxr_c[2][E_], uxz_c[2][E_];
    #pragma unroll
    for (int j = 0; j < E_; j++) {
        W10 wxr = ldrow(c_w + 0   + j * 12);
        W10 wxz = ldrow(c_w + 120 + j * 12);
        float br = c_w[360 + j], bz = c_w[370 + j];
        #pragma unroll
        for (int u = 0; u < 2; u++) {
            float2 r = make_float2(br, 0.f);
            float2 z = make_float2(bz, 0.f);
            r = dotw(wxr, xp_c[u], r);
            z = dotw(wxz, xp_c[u], z);
            uxr_c[u][j] = r.x + r.y;
            uxz_c[u][j] = z.x + z.y;
        }
    }

    #pragma unroll 1
    for (int t = 0; t < T_; t++) {
        const int d = t & 3;
        if (t + 2 < T_) {
            stage(t + 2, (t + 2) & 3);
            asm volatile("cp.async.wait_group 1;");   // buffer t+1 ready
        } else {
            asm volatile("cp.async.wait_group 0;");
        }

        // ---- independent slab: x(t+1) + its r/z x-side partials ----
        float2 xp_n[2][5];
        float uxr_n[2][E_], uxz_n[2][E_];
        if (t + 1 < T_) {
            const float* xbn = &sx[(t + 1) & 3][0];
            #pragma unroll
            for (int u = 0; u < 2; u++) {
                const float* xr = xbn + (tid + 32 * u) * RS;
                #pragma unroll
                for (int i = 0; i < 5; i++)
                    xp_n[u][i] = *reinterpret_cast<const float2*>(xr + 2 * i);
            }
            #pragma unroll
            for (int j = 0; j < E_; j++) {
                W10 wxr = ldrow(c_w + 0   + j * 12);
                W10 wxz = ldrow(c_w + 120 + j * 12);
                float br = c_w[360 + j], bz = c_w[370 + j];
                #pragma unroll
                for (int u = 0; u < 2; u++) {
                    float2 r = make_float2(br, 0.f);
                    float2 z = make_float2(bz, 0.f);
                    r = dotw(wxr, xp_n[u], r);
                    z = dotw(wxz, xp_n[u], z);
                    uxr_n[u][j] = r.x + r.y;
                    uxz_n[u][j] = z.x + z.y;
                }
            }
        }

        // ---- dependent chain for step t ----
        // z-gate: zp_j = uxz + Ahz_j . h ; hz = h * sigmoid(zp)
        float2 hzp[2][5];
        {
            float hztmp[2][E_];
            #pragma unroll
            for (int j = 0; j < E_; j++) {
                W10 whz = ldrow(Ahz + j * 12);
                #pragma unroll
                for (int u = 0; u < 2; u++) {
                    float2 z = make_float2(uxz_c[u][j], 0.f);
                    z = dotw(whz, h[u], z);
                    hztmp[u][j] = F2AT(h[u], j) * sigf(z.x + z.y);
                }
            }
            #pragma unroll
            for (int u = 0; u < 2; u++)
                #pragma unroll
                for (int i = 0; i < 5; i++)
                    hzp[u][i] = make_float2(hztmp[u][2 * i], hztmp[u][2 * i + 1]);
        }

        // r-gate + candidate + blend (into hn; old h still read by r-dots)
        const float* __restrict__ ab = &sa[d][0];
        float hn[2][E_];
        #pragma unroll
        for (int j = 0; j < E_; j++) {
            W10 whr = ldrow(Ahr + j * 12);
            W10 wxh = ldrow(c_w + 240 + j * 12);
            W10 whh = ldrow(Ahh + j * 12);
            float bh = c_w[380 + j];
            #pragma unroll
            for (int u = 0; u < 2; u++) {
                float2 r = make_float2(uxr_c[u][j], 0.f);
                r = dotw(whr, h[u], r);
                float2 c = make_float2(bh, 0.f);
                c = dotw(wxh, xp_c[u], c);
                c = dotw(whh, hzp[u], c);
                float av = ab[(tid + 32 * u) * RS + j];
                float Ra = av * sigf(r.x + r.y);
                float hc = tanh_ap(c.x + c.y);
                float ho = F2AT(h[u], j);
                hn[u][j] = fmaf(Ra, hc - ho, ho);
            }
        }

        // commit new h (packed) + rotate pipeline registers
        #pragma unroll
        for (int u = 0; u < 2; u++)
            #pragma unroll
            for (int i = 0; i < 5; i++)
                h[u][i] = make_float2(hn[u][2 * i], hn[u][2 * i + 1]);

        #pragma unroll
        for (int u = 0; u < 2; u++) {
            #pragma unroll
            for (int i = 0; i < 5; i++) xp_c[u][i] = xp_n[u][i];
            #pragma unroll
            for (int j = 0; j < E_; j++) {
                uxr_c[u][j] = uxr_n[u][j];
                uxz_c[u][j] = uxz_n[u][j];
            }
        }
    }

    // write out: rows b0+tid and b0+tid+32, 5 float2 each
    float2* __restrict__ po = reinterpret_cast<float2*>(out);
    #pragma unroll
    for (int u = 0; u < 2; u++) {
        float2* p = po + (size_t)(b0 + tid + 32 * u) * 5;
        #pragma unroll
        for (int i = 0; i < 5; i++) p[i] = h[u][i];
    }
}

extern "C" void kernel_launch(void* const* d_in, const int* in_sizes, int n_in,
                              void* d_out, int out_size) {
    const float* gx   = (const float*)d_in[0];
    const float* ga   = (const float*)d_in[1];
    const float* h0   = (const float*)d_in[2];
    const float* Wi_r = (const float*)d_in[3];
    const float* bi_r = (const float*)d_in[4];
    const float* Wh_r = (const float*)d_in[5];
    const float* Ws_r = (const float*)d_in[6];
    const float* bs_r = (const float*)d_in[7];
    const float* Wi_z = (const float*)d_in[8];
    const float* bi_z = (const float*)d_in[9];
    const float* Wh_z = (const float*)d_in[10];
    const float* Ws_z = (const float*)d_in[11];
    const float* bs_z = (const float*)d_in[12];
    const float* Wi_h = (const float*)d_in[13];
    const float* bi_h = (const float*)d_in[14];
    const float* Wh_h = (const float*)d_in[15];
    const float* Wt_h = (const float*)d_in[16];
    const float* bt_h = (const float*)d_in[17];
    float* out = (float*)d_out;

    augru_precompute<<<1, 640>>>(Wi_r, bi_r, Wh_r, Ws_r, bs_r,
                                 Wi_z, bi_z, Wh_z, Ws_z, bs_z,
                                 Wi_h, bi_h, Wh_h, Wt_h, bt_h);

    void* g_ptr = nullptr;
    cudaGetSymbolAddress(&g_ptr, g_w2);
    cudaMemcpyToSymbolAsync(c_w, g_ptr, 390 * sizeof(float), 0,
                            cudaMemcpyDeviceToDevice, 0);

    augru_main<<<B_ / EB, NB>>>(gx, ga, h0, out);
}

// round 13
// speedup vs baseline: 2.4308x; 2.4308x over previous
#include <cuda_runtime.h>
#include <cstdint>

// AUGRU: B=65536, T=50, E=10.
// Fold: (x@Wi + bi + h@Wh)@Ws + bs == x@(Wi@Ws) + h@(Wh@Ws) + (bi@Ws + bs)
// R13 = R9 (feature-packed f32x2 dots, 2 elems/thread, tanh.approx, 1024
// warps, double-buffered cp.async staging) with ALL six folded matrices +
// biases on the constant port (no smem weight reads at all -> L1 serves only
// the staged x/a data), and both __syncwarp()s removed (each thread reads
// only rows it staged itself; cp.async completion is per-thread).

#define E_  10
#define T_  50
#define B_  65536
#define NB  32           // threads per block
#define EB  64           // batch elems per block (2 per thread)
#define RS  10           // floats per row per timestep
#define ROWB (T_*E_)     // 500 floats per batch row

// g_w2 layout (transposed A^T[j][k], row stride 12, 16B-aligned rows):
//   Axr@0, Axz@120, Axh@240, Ahr@360, Ahz@480, Ahh@600
//   biases: br@720, bz@730, bh@740
__device__ float g_w2[752];

// constant mirror of the whole weight set
__constant__ float c_w[752];

__global__ void augru_precompute(
    const float* __restrict__ Wi_r, const float* __restrict__ bi_r,
    const float* __restrict__ Wh_r, const float* __restrict__ Ws_r, const float* __restrict__ bs_r,
    const float* __restrict__ Wi_z, const float* __restrict__ bi_z,
    const float* __restrict__ Wh_z, const float* __restrict__ Ws_z, const float* __restrict__ bs_z,
    const float* __restrict__ Wi_h, const float* __restrict__ bi_h,
    const float* __restrict__ Wh_h, const float* __restrict__ Wt_h, const float* __restrict__ bt_h)
{
    int tid = threadIdx.x;
    if (tid < 600) {
        int m = tid / 100, rem = tid % 100, j = rem / 10, k = rem % 10;
        const float* W1; const float* W2; int dst;
        switch (m) {
            case 0: W1 = Wi_r; W2 = Ws_r; dst = 0;   break;  // Axr
            case 1: W1 = Wh_r; W2 = Ws_r; dst = 360; break;  // Ahr
            case 2: W1 = Wi_z; W2 = Ws_z; dst = 120; break;  // Axz
            case 3: W1 = Wh_z; W2 = Ws_z; dst = 480; break;  // Ahz
            case 4: W1 = Wi_h; W2 = Wt_h; dst = 240; break;  // Axh
            default: W1 = Wh_h; W2 = Wt_h; dst = 600; break; // Ahh
        }
        float acc = 0.f;
        #pragma unroll
        for (int mm = 0; mm < E_; mm++)
            acc += W1[k * E_ + mm] * W2[mm * E_ + j];
        g_w2[dst + j * 12 + k] = acc;
    } else if (tid < 630) {
        int g = (tid - 600) / 10, j = (tid - 600) % 10;
        const float* bi; const float* Ws; const float* bs;
        if (g == 0)      { bi = bi_r; Ws = Ws_r; bs = bs_r; }
        else if (g == 1) { bi = bi_z; Ws = Ws_z; bs = bs_z; }
        else             { bi = bi_h; Ws = Wt_h; bs = bt_h; }
        float acc = bs[j];
        #pragma unroll
        for (int mm = 0; mm < E_; mm++)
            acc += bi[mm] * Ws[mm * E_ + j];
        g_w2[720 + g * 10 + j] = acc;
    }
}

__device__ __forceinline__ float2 fma2(float2 a, float2 b, float2 c) {
    unsigned long long ua = *reinterpret_cast<unsigned long long*>(&a);
    unsigned long long ub = *reinterpret_cast<unsigned long long*>(&b);
    unsigned long long uc = *reinterpret_cast<unsigned long long*>(&c);
    unsigned long long ud;
    asm("fma.rn.f32x2 %0, %1, %2, %3;" : "=l"(ud) : "l"(ua), "l"(ub), "l"(uc));
    return *reinterpret_cast<float2*>(&ud);
}

__device__ __forceinline__ float tanh_ap(float x) {
    float y;
    asm("tanh.approx.f32 %0, %1;" : "=f"(y) : "f"(x));
    return y;
}
__device__ __forceinline__ float sigf(float x) {
    return fmaf(0.5f, tanh_ap(0.5f * x), 0.5f);
}

// one 10-float weight row, loaded once (f4,f4,f2) from the constant bank
struct W10 { float4 a; float4 b; float2 c; };

__device__ __forceinline__ W10 ldrow(const float* __restrict__ w) {
    W10 r;
    r.a = *reinterpret_cast<const float4*>(w);
    r.b = *reinterpret_cast<const float4*>(w + 4);
    r.c = *reinterpret_cast<const float2*>(w + 8);
    return r;
}

// dot of loaded row with feature-packed vector v[5] into (even,odd) acc
__device__ __forceinline__ float2 dotw(const W10& w, const float2* __restrict__ v, float2 acc) {
    acc = fma2(make_float2(w.a.x, w.a.y), v[0], acc);
    acc = fma2(make_float2(w.a.z, w.a.w), v[1], acc);
    acc = fma2(make_float2(w.b.x, w.b.y), v[2], acc);
    acc = fma2(make_float2(w.b.z, w.b.w), v[3], acc);
    acc = fma2(w.c,                       v[4], acc);
    return acc;
}

__device__ __forceinline__ void cpa8(uint32_t smem_addr, const void* gptr) {
    asm volatile("cp.async.ca.shared.global [%0], [%1], 8;" :: "r"(smem_addr), "l"(gptr));
}

__global__ void __launch_bounds__(NB) augru_main(
    const float* __restrict__ gx,   // [B, T, E]
    const float* __restrict__ ga,   // [B, T, E]
    const float* __restrict__ h0,   // [1, E]
    float* __restrict__ out)        // [B, E]
{
    __shared__ __align__(16) float sx[2][EB * RS];   // [buf][row][10]
    __shared__ __align__(16) float sa[2][EB * RS];

    const int tid = threadIdx.x;
    const int b0  = blockIdx.x * EB;

    const uint32_t sxa = (uint32_t)__cvta_generic_to_shared(&sx[0][0]);
    const uint32_t saa = (uint32_t)__cvta_generic_to_shared(&sa[0][0]);
    const char* gxb = (const char*)gx + (size_t)b0 * (ROWB * 4);
    const char* gab = (const char*)ga + (size_t)b0 * (ROWB * 4);

    // stage timestep t into buffer d: thread copies its own rows tid, tid+32
    auto stage = [&](int t, int d) {
        const int tb = t * (RS * 4);
        #pragma unroll
        for (int k = 0; k < 2; k++) {
            const int row = tid + k * NB;
            const uint32_t sbase = (uint32_t)((d * (EB * RS) + row * RS) * 4);
            const size_t gbase = (size_t)row * (ROWB * 4) + tb;
            #pragma unroll
            for (int c = 0; c < 5; c++) {
                cpa8(sxa + sbase + c * 8, gxb + gbase + c * 8);
                cpa8(saa + sbase + c * 8, gab + gbase + c * 8);
            }
        }
        asm volatile("cp.async.commit_group;");
    };

    stage(0, 0);

    // h feature-packed for 2 elements: unit u = batch row b0 + tid + 32u
    float2 h[2][5];
    #pragma unroll
    for (int i = 0; i < 5; i++) {
        float2 v = make_float2(h0[2 * i], h0[2 * i + 1]);
        h[0][i] = v; h[1][i] = v;
    }

    #pragma unroll 1
    for (int t = 0; t < T_; t++) {
        const int d = t & 1;
        if (t + 1 < T_) {
            stage(t + 1, d ^ 1);
            asm volatile("cp.async.wait_group 1;");
        } else {
            asm volatile("cp.async.wait_group 0;");
        }
        // no __syncwarp(): every thread reads only the rows it staged itself,
        // and cp.async completion is per-thread after wait_group.

        const float* __restrict__ xb = &sx[d][0];
        const float* __restrict__ ab = &sa[d][0];

        // x features, naturally packed per element (rows are 40B, 8B-aligned)
        float2 xp[2][5];
        #pragma unroll
        for (int u = 0; u < 2; u++) {
            const float* xr = xb + (tid + 32 * u) * RS;
            #pragma unroll
            for (int i = 0; i < 5; i++)
                xp[u][i] = *reinterpret_cast<const float2*>(xr + 2 * i);
        }

        // ---- loop 1: rp, zp pre-activations; each row loaded once, used 2x ----
        float rp[2][E_], zp[2][E_];
        #pragma unroll
        for (int j = 0; j < E_; j++) {
            W10 wxr = ldrow(c_w + 0   + j * 12);
            W10 whr = ldrow(c_w + 360 + j * 12);
            W10 wxz = ldrow(c_w + 120 + j * 12);
            W10 whz = ldrow(c_w + 480 + j * 12);
            float br = c_w[720 + j], bz = c_w[730 + j];
            #pragma unroll
            for (int u = 0; u < 2; u++) {
                float2 r = make_float2(br, 0.f);
                float2 z = make_float2(bz, 0.f);
                r = dotw(wxr, xp[u], r);
                r = dotw(whr, h[u],  r);
                z = dotw(wxz, xp[u], z);
                z = dotw(whz, h[u],  z);
                rp[u][j] = r.x + r.y;
                zp[u][j] = z.x + z.y;
            }
        }

        // ---- loop 2: hz = h * sigmoid(zp) ----
        float2 hz[2][5];
        #pragma unroll
        for (int u = 0; u < 2; u++)
            #pragma unroll
            for (int i = 0; i < 5; i++)
                hz[u][i] = make_float2(h[u][i].x * sigf(zp[u][2 * i]),
                                       h[u][i].y * sigf(zp[u][2 * i + 1]));

        // ---- loop 3: candidate pre-activation ----
        float hcp[2][E_];
        #pragma unroll
        for (int j = 0; j < E_; j++) {
            W10 wxh = ldrow(c_w + 240 + j * 12);
            W10 whh = ldrow(c_w + 600 + j * 12);
            float bh = c_w[740 + j];
            #pragma unroll
            for (int u = 0; u < 2; u++) {
                float2 c = make_float2(bh, 0.f);
                c = dotw(wxh, xp[u], c);
                c = dotw(whh, hz[u], c);
                hcp[u][j] = c.x + c.y;
            }
        }

        // ---- loop 4: blend ----
        #pragma unroll
        for (int u = 0; u < 2; u++) {
            const float* ar = ab + (tid + 32 * u) * RS;
            #pragma unroll
            for (int i = 0; i < 5; i++) {
                float2 ap = *reinterpret_cast<const float2*>(ar + 2 * i);
                float Ra0 = ap.x * sigf(rp[u][2 * i]);
                float Ra1 = ap.y * sigf(rp[u][2 * i + 1]);
                float hc0 = tanh_ap(hcp[u][2 * i]);
                float hc1 = tanh_ap(hcp[u][2 * i + 1]);
                h[u][i].x = fmaf(Ra0, hc0 - h[u][i].x, h[u][i].x);
                h[u][i].y = fmaf(Ra1, hc1 - h[u][i].y, h[u][i].y);
            }
        }
    }

    // write out: rows b0+tid and b0+tid+32, 5 float2 each
    float2* __restrict__ po = reinterpret_cast<float2*>(out);
    #pragma unroll
    for (int u = 0; u < 2; u++) {
        float2* p = po + (size_t)(b0 + tid + 32 * u) * 5;
        #pragma unroll
        for (int i = 0; i < 5; i++) p[i] = h[u][i];
    }
}

extern "C" void kernel_launch(void* const* d_in, const int* in_sizes, int n_in,
                              void* d_out, int out_size) {
    const float* gx   = (const float*)d_in[0];
    const float* ga   = (const float*)d_in[1];
    const float* h0   = (const float*)d_in[2];
    const float* Wi_r = (const float*)d_in[3];
    const float* bi_r = (const float*)d_in[4];
    const float* Wh_r = (const float*)d_in[5];
    const float* Ws_r = (const float*)d_in[6];
    const float* bs_r = (const float*)d_in[7];
    const float* Wi_z = (const float*)d_in[8];
    const float* bi_z = (const float*)d_in[9];
    const float* Wh_z = (const float*)d_in[10];
    const float* Ws_z = (const float*)d_in[11];
    const float* bs_z = (const float*)d_in[12];
    const float* Wi_h = (const float*)d_in[13];
    const float* bi_h = (const float*)d_in[14];
    const float* Wh_h = (const float*)d_in[15];
    const float* Wt_h = (const float*)d_in[16];
    const float* bt_h = (const float*)d_in[17];
    float* out = (float*)d_out;

    augru_precompute<<<1, 640>>>(Wi_r, bi_r, Wh_r, Ws_r, bs_r,
                                 Wi_z, bi_z, Wh_z, Ws_z, bs_z,
                                 Wi_h, bi_h, Wh_h, Wt_h, bt_h);

    void* g_ptr = nullptr;
    cudaGetSymbolAddress(&g_ptr, g_w2);
    cudaMemcpyToSymbolAsync(c_w, g_ptr, 752 * sizeof(float), 0,
                            cudaMemcpyDeviceToDevice, 0);

    augru_main<<<B_ / EB, NB>>>(gx, ga, h0, out);
}